// round 16
// baseline (speedup 1.0000x reference)
#include <cuda_runtime.h>
#include <math.h>

#define G   640
#define NXK 320
#define MK  65536
#define NCK 8
#define NTK 8
#define LB  4            // FFT lines per block (one coil-quad)
#define FT  256          // FFT kernel threads
#define LSA 676          // bufA line stride (float2): >=675, == 4 mod 16 (conflict-free loads)
#define LSB 780          // bufB line stride (float2): 5 * 156
#define SUBA 135         // bufA sub-FFT stride (pad1 layout: m + (m>>4), max 134)
#define SUBB 156         // bufB sub-FFT stride (pad4 layout: m + 4*(m>>4), max 155)

// ---- scratch (device globals; no runtime allocation) ----
// d_grids: [t][cq][i][j][c4]  (coil quads innermost -> 32B-contiguous scatter targets)
__device__ float2 d_grids[(size_t)NTK * 2 * G * G * 4];        // ~210 MB
// d_buf1:  [t][cq][row][cy][c4]
__device__ float2 d_buf1 [(size_t)NTK * 2 * G * NXK * 4];      // ~105 MB
// d_buf2:  [t][cx][cy][c8]
__device__ float2 d_buf2 [(size_t)NTK * NXK * NXK * NCK];      // ~52 MB
__device__ float2 d_fimg [(size_t)NTK * NXK * NXK];            // ~6.6 MB

__constant__ float2 W5c[5] = {
    { 1.0f,                   0.0f },
    { 0.30901699437494745f,   0.9510565162951535f },
    {-0.8090169943749473f,    0.5877852522924731f },
    {-0.8090169943749475f,   -0.587785252292473f  },
    { 0.30901699437494723f,  -0.9510565162951536f }
};

__device__ __forceinline__ float2 cadd(float2 a, float2 b) { return make_float2(a.x + b.x, a.y + b.y); }
__device__ __forceinline__ float2 csub(float2 a, float2 b) { return make_float2(a.x - b.x, a.y - b.y); }
__device__ __forceinline__ float2 cmul(float2 a, float2 b) { return make_float2(a.x * b.x - a.y * b.y, a.x * b.y + a.y * b.x); }
__device__ __forceinline__ float2 cmuli(float2 a) { return make_float2(-a.y, a.x); }   // * (+i)

// padded index maps
__device__ __forceinline__ int idxp1(int m) { return m + (m >> 4); }       // bufA r4a-out
__device__ __forceinline__ int idxp4(int m) { return m + 4 * (m >> 4); }   // bufB r4b-out

// ---------------- zero grids ----------------
__global__ void zero_kernel() {
    size_t i = (size_t)blockIdx.x * blockDim.x + threadIdx.x;
    float4* p = reinterpret_cast<float4*>(d_grids);
    size_t n4 = (size_t)NTK * 2 * G * G * 4 / 2;
    if (i < n4) p[i] = make_float4(0.f, 0.f, 0.f, 0.f);
}

// ---------------- gridding (scatter, red.add.v4.f32 to contiguous coil quads) ----------------
__device__ __forceinline__ void redv4(float2* p, float2 a, float2 b) {
    asm volatile("red.global.add.v4.f32 [%0], {%1, %2, %3, %4};"
                 :: "l"(p), "f"(a.x), "f"(a.y), "f"(b.x), "f"(b.y) : "memory");
}

__global__ void grid_kernel(const float* __restrict__ kr, const float* __restrict__ ki,
                            const float* __restrict__ traj, const float* __restrict__ dcf) {
    int m = blockIdx.x * blockDim.x + threadIdx.x;
    int t = blockIdx.y;
    if (m >= MK) return;
    float tx = traj[m * 16 + t];
    float ty = traj[m * 16 + 8 + t];
    float w  = dcf[m * 8 + t];

    float u = (tx + 0.5f) * (float)G;
    float v = (ty + 0.5f) * (float)G;
    float u0 = floorf(u), v0 = floorf(v);
    float du = u - u0, dv = v - v0;
    int i0 = ((int)u0) % G; if (i0 < 0) i0 += G;
    int j0 = ((int)v0) % G; if (j0 < 0) j0 += G;
    int i1 = (i0 + 1 == G) ? 0 : i0 + 1;
    int j1 = (j0 + 1 == G) ? 0 : j0 + 1;

    float w00 = (1.f - du) * (1.f - dv) * w;
    float w10 = du * (1.f - dv) * w;
    float w01 = (1.f - du) * dv * w;
    float w11 = du * dv * w;

#pragma unroll
    for (int cq = 0; cq < 2; cq++) {
        float2 d[4];
#pragma unroll
        for (int c4 = 0; c4 < 4; c4++) {
            int c = cq * 4 + c4;
            d[c4] = make_float2(kr[c * MK + m], ki[c * MK + m]);
        }
        float2* base = d_grids + ((size_t)(t * 2 + cq) * G * G) * 4;
        float2* p00 = base + (size_t)(i0 * G + j0) * 4;
        float2* p10 = base + (size_t)(i1 * G + j0) * 4;
        float2* p01 = base + (size_t)(i0 * G + j1) * 4;
        float2* p11 = base + (size_t)(i1 * G + j1) * 4;
#define CORNER(P, W) \
        redv4(P,     make_float2(d[0].x*(W), d[0].y*(W)), make_float2(d[1].x*(W), d[1].y*(W))); \
        redv4(P + 2, make_float2(d[2].x*(W), d[2].y*(W)), make_float2(d[3].x*(W), d[3].y*(W)));
        CORNER(p00, w00)
        CORNER(p10, w10)
        CORNER(p01, w01)
        CORNER(p11, w11)
#undef CORNER
    }
}

// ======== 640-pt FFT (sign = +i, unnormalized), bank-conflict-free stage layouts =========
// bufA: input lines (stride LSA); later holds r4a output (sub stride SUBA, pad1 map)
// bufB: radix5 output (sub stride 128); later holds r4b/fused8 output (sub stride SUBB, pad4 map)

// Step A: 128 radix-5 DFTs per line + twiddle.  A(input) -> B(sub 128)
__device__ __forceinline__ void step_radix5(const float2* SA, float2* SB, int tid) {
    for (int i = tid; i < LB * 128; i += FT) {
        int l = i >> 7, n2 = i & 127;
        const float2* a = SA + l * LSA + n2;
        float2 x0 = a[0];
        float2 x1 = a[128];
        float2 x2 = a[256];
        float2 x3 = a[384];
        float2 x4 = a[512];
        float ang = (float)n2 * 9.817477042468103e-3f;   // 2*pi/640
        float sn, cs; __sincosf(ang, &sn, &cs);
        float2 w1 = make_float2(cs, sn);
        float2 w2 = cmul(w1, w1);
        float2 w3 = cmul(w2, w1);
        float2 w4 = cmul(w2, w2);
        float2 wp[5] = { make_float2(1.f, 0.f), w1, w2, w3, w4 };
        float2* outb = SB + l * LSB + n2;
#pragma unroll
        for (int k1 = 0; k1 < 5; k1++) {
            float2 acc = x0;
            int r = 0;
            float2 xs[4] = {x1, x2, x3, x4};
#pragma unroll
            for (int n1 = 1; n1 < 5; n1++) {
                r += k1; if (r >= 5) r -= 5;
                float2 wv = W5c[r];
                acc.x += xs[n1 - 1].x * wv.x - xs[n1 - 1].y * wv.y;
                acc.y += xs[n1 - 1].x * wv.y + xs[n1 - 1].y * wv.x;
            }
            outb[k1 * 128] = (k1 == 0) ? acc : cmul(acc, wp[k1]);
        }
    }
}

// Stage r4a: radix4 (N=128, S=1).  B(sub 128) -> A(sub SUBA, pad1)
__device__ __forceinline__ void stage_r4a(const float2* SB, float2* SA, int tid) {
    for (int i = tid; i < LB * 160; i += FT) {
        int l = i / 160, r = i - l * 160;
        int f = r >> 5, p = r & 31;
        const float2* src = SB + l * LSB + f * 128;
        float2 x0 = src[p];
        float2 x1 = src[p + 32];
        float2 x2 = src[p + 64];
        float2 x3 = src[p + 96];
        float2 t0 = cadd(x0, x2);
        float2 t1 = csub(x0, x2);
        float2 t2 = cadd(x1, x3);
        float2 t3 = cmuli(csub(x1, x3)); // +i*(x1-x3)
        float2 y0 = cadd(t0, t2);
        float2 y1 = cadd(t1, t3);
        float2 y2 = csub(t0, t2);
        float2 y3 = csub(t1, t3);
        float ang = 4.908738521234052e-2f * (float)p;    // 2*pi/128
        float s1, c1; __sincosf(ang, &s1, &c1);
        float c2 = c1 * c1 - s1 * s1, s2 = 2.f * c1 * s1;
        float c3 = c2 * c1 - s2 * s1, s3 = c2 * s1 + s2 * c1;
        float2* dst = SA + l * LSA + f * SUBA;
        int m = 4 * p;
        dst[idxp1(m + 0)] = y0;
        dst[idxp1(m + 1)] = make_float2(y1.x * c1 - y1.y * s1, y1.x * s1 + y1.y * c1);
        dst[idxp1(m + 2)] = make_float2(y2.x * c2 - y2.y * s2, y2.x * s2 + y2.y * c2);
        dst[idxp1(m + 3)] = make_float2(y3.x * c3 - y3.y * s3, y3.x * s3 + y3.y * c3);
    }
}

// Stage r4b: radix4 (N=32, S=4).  A(pad1, legs +34k) -> B(sub SUBB, pad4)
__device__ __forceinline__ void stage_r4b(const float2* SA, float2* SB, int tid) {
    for (int i = tid; i < LB * 160; i += FT) {
        int l = i / 160, r = i - l * 160;
        int f = r >> 5, b = r & 31;
        int p = b >> 2, q = b & 3;
        const float2* src = SA + l * LSA + f * SUBA + idxp1(q + 4 * p);
        float2 x0 = src[0];
        float2 x1 = src[34];
        float2 x2 = src[68];
        float2 x3 = src[102];
        float2 t0 = cadd(x0, x2);
        float2 t1 = csub(x0, x2);
        float2 t2 = cadd(x1, x3);
        float2 t3 = cmuli(csub(x1, x3));
        float2 y0 = cadd(t0, t2);
        float2 y1 = cadd(t1, t3);
        float2 y2 = csub(t0, t2);
        float2 y3 = csub(t1, t3);
        float ang = 0.19634954084936207f * (float)p;     // 2*pi/32
        float s1, c1; __sincosf(ang, &s1, &c1);
        float c2 = c1 * c1 - s1 * s1, s2 = 2.f * c1 * s1;
        float c3 = c2 * c1 - s2 * s1, s3 = c2 * s1 + s2 * c1;
        float2* dst = SB + l * LSB + f * SUBB;
        int mb = q + 16 * p;    // m' = q + 4*(4p+j) = q + 16p + 4j
        dst[idxp4(mb + 0)]  = y0;
        dst[idxp4(mb + 4)]  = make_float2(y1.x * c1 - y1.y * s1, y1.x * s1 + y1.y * c1);
        dst[idxp4(mb + 8)]  = make_float2(y2.x * c2 - y2.y * s2, y2.x * s2 + y2.y * c2);
        dst[idxp4(mb + 12)] = make_float2(y3.x * c3 - y3.y * s3, y3.x * s3 + y3.y * c3);
    }
}

// Fused final stage: 8-pt DFT on chain q+16j (phys q+20j in pad4), in place, PRUNED:
// only outputs j in {0,1,6,7} (k2 in [0,32) u [96,128)) are ever gathered.
__device__ __forceinline__ void stage_fused8(float2* SB, int tid) {
    const float2 w8_1 = make_float2( 0.7071067811865476f, 0.7071067811865476f);
    const float2 w8_3 = make_float2(-0.7071067811865476f, 0.7071067811865476f);
    for (int i = tid; i < LB * 5 * 16; i += FT) {
        int q = i & 15, g = i >> 4;
        int f = g % 5, l = g / 5;
        float2* B = SB + l * LSB + f * SUBB + q;   // legs at +20*j
        float2 a0 = B[0],   a1 = B[20],  a2 = B[40],  a3 = B[60];
        float2 a4 = B[80],  a5 = B[100], a6 = B[120], a7 = B[140];
        // radix4<8,16> p=0: inputs a0,a2,a4,a6
        float2 t0 = cadd(a0, a4), t1 = csub(a0, a4);
        float2 t2 = cadd(a2, a6), t3 = cmuli(csub(a2, a6));
        float2 b0 = cadd(t0, t2), b1 = cadd(t1, t3);
        float2 b2 = csub(t0, t2), b3 = csub(t1, t3);
        // radix4<8,16> p=1 (twiddles w8^k): inputs a1,a3,a5,a7
        float2 u0 = cadd(a1, a5), u1 = csub(a1, a5);
        float2 u2 = cadd(a3, a7), u3 = cmuli(csub(a3, a7));
        float2 b4 = cadd(u0, u2);
        float2 b5 = cmul(cadd(u1, u3), w8_1);
        float2 b6 = cmuli(csub(u0, u2));
        float2 b7 = cmul(csub(u1, u3), w8_3);
        // pruned final radix-2: keep outputs at j = 0,1,6,7
        B[0]   = cadd(b0, b4);   // j=0 : k2 = q
        B[20]  = cadd(b1, b5);   // j=1 : k2 = q+16
        B[120] = csub(b2, b6);   // j=6 : k2 = q+96
        B[140] = csub(b3, b7);   // j=7 : k2 = q+112
    }
}

__device__ __forceinline__ void fft640(float2* SA, float2* SB, int tid) {
    step_radix5(SA, SB, tid);  __syncthreads();
    stage_r4a(SB, SA, tid);    __syncthreads();
    stage_r4b(SA, SB, tid);    __syncthreads();
    stage_fused8(SB, tid);     __syncthreads();
    // X[5*k2+k1] at SB[l*LSB + k1*SUBB + idxp4(k2)], valid for k2 in [0,32) u [96,128)
}

// gather address for kept output k
__device__ __forceinline__ int gaddr(int k, int l) {
    int k1 = k % 5, k2 = k / 5;
    return l * LSB + k1 * SUBB + idxp4(k2);
}

// ---------------- pass 1: FFT rows, keep cropped 320 columns ----------------
__global__ void fft_rows_kernel() {
    __shared__ float2 SA[LB * LSA];
    __shared__ float2 SB[LB * LSB];
    int tid = threadIdx.x;
    int tq  = blockIdx.x / G;      // t*2 + cq
    int row = blockIdx.x % G;

    const float2* in = d_grids + ((size_t)tq * G + row) * G * 4;
    for (int v = tid; v < G * 4; v += FT) {
        int c = v & 3, j = v >> 2;
        SA[c * LSA + j] = in[v];
    }
    __syncthreads();
    fft640(SA, SB, tid);

    float2* out = d_buf1 + ((size_t)tq * G + row) * NXK * 4;
    for (int v = tid; v < NXK * 4; v += FT) {
        int c = v & 3, cy = v >> 2;
        int k = (cy < 160) ? cy + 480 : cy - 160;   // (cy+480) % 640
        out[v] = SB[gaddr(k, c)];
    }
}

// ---------------- pass 2: FFT columns, keep cropped 320 rows ----------------
__global__ void fft_cols_kernel() {
    __shared__ float2 SA[LB * LSA];
    __shared__ float2 SB[LB * LSB];
    int tid = threadIdx.x;
    int tq = blockIdx.x / NXK;
    int cy = blockIdx.x % NXK;

    const float2* in = d_buf1 + (size_t)tq * G * NXK * 4 + (size_t)cy * 4;
    for (int v = tid; v < G * 4; v += FT) {
        int c = v & 3, i = v >> 2;
        SA[c * LSA + i] = in[(size_t)i * NXK * 4 + c];
    }
    __syncthreads();
    fft640(SA, SB, tid);

    int t = tq >> 1, cq = tq & 1;
    float2* out = d_buf2 + (size_t)t * NXK * NXK * NCK + cq * 4;
    for (int v = tid; v < NXK * 4; v += FT) {
        int c = v & 3, cx = v >> 2;
        int k = (cx < 160) ? cx + 480 : cx - 160;
        out[((size_t)cx * NXK + cy) * NCK + c] = SB[gaddr(k, c)];
    }
}

// ---------------- coil combine + sign + deapodization + 1/G^2 ----------------
__global__ void combine_kernel(const float* __restrict__ csr, const float* __restrict__ csi) {
    int pix = blockIdx.x * blockDim.x + threadIdx.x;
    int t = blockIdx.y;
    if (pix >= NXK * NXK) return;
    int cx = pix / NXK, cy = pix % NXK;

    const float4* p = reinterpret_cast<const float4*>(d_buf2 + ((size_t)t * NXK * NXK + pix) * NCK);
    float2 acc = make_float2(0.f, 0.f);
#pragma unroll
    for (int h = 0; h < 4; h++) {            // 2 coils per float4
        float4 vv = p[h];
        int c0 = h * 2, c1 = h * 2 + 1;
        float cr0 = csr[c0 * NXK * NXK + pix], ci0 = csi[c0 * NXK * NXK + pix];
        float cr1 = csr[c1 * NXK * NXK + pix], ci1 = csi[c1 * NXK * NXK + pix];
        acc.x += cr0 * vv.x + ci0 * vv.y + cr1 * vv.z + ci1 * vv.w;
        acc.y += cr0 * vv.y - ci0 * vv.x + cr1 * vv.w - ci1 * vv.z;
    }
    float xv = (float)(cx - 160) * (1.0f / 640.0f);
    float yv = (float)(cy - 160) * (1.0f / 640.0f);
    float sx = (cx == 160) ? 1.0f : sinpif(xv) / (3.14159265358979f * xv);
    float sy = (cy == 160) ? 1.0f : sinpif(yv) / (3.14159265358979f * yv);
    float sgn = ((cx + cy) & 1) ? -1.0f : 1.0f;
    float scale = sgn / (409600.0f * (sx * sx) * (sy * sy));
    d_fimg[(size_t)t * NXK * NXK + pix] = make_float2(acc.x * scale, acc.y * scale);
}

// ---------------- motion warp + frame sum ----------------
__global__ void warp_kernel(const float* __restrict__ motions, float* __restrict__ out) {
    int pix = blockIdx.x * blockDim.x + threadIdx.x;
    if (pix >= NXK * NXK) return;
    int x = pix / NXK, y = pix % NXK;

    float2 acc = make_float2(0.f, 0.f);
#pragma unroll
    for (int t = 0; t < NTK; t++) {
        float f0 = motions[(pix * 2 + 0) * NTK + t];
        float f1 = motions[(pix * 2 + 1) * NTK + t];
        float xs = fminf(fmaxf((float)x + f0, 0.f), 319.f);
        float ys = fminf(fmaxf((float)y + f1, 0.f), 319.f);
        float x0f = floorf(xs), y0f = floorf(ys);
        int x0 = (int)x0f, y0 = (int)y0f;
        int x1 = min(x0 + 1, 319), y1 = min(y0 + 1, 319);
        float dx = xs - x0f, dy = ys - y0f;
        const float2* im = d_fimg + (size_t)t * NXK * NXK;
        float2 v00 = im[x0 * NXK + y0];
        float2 v10 = im[x1 * NXK + y0];
        float2 v01 = im[x0 * NXK + y1];
        float2 v11 = im[x1 * NXK + y1];
        float w00 = (1.f - dx) * (1.f - dy), w10 = dx * (1.f - dy);
        float w01 = (1.f - dx) * dy,         w11 = dx * dy;
        acc.x += w00 * v00.x + w10 * v10.x + w01 * v01.x + w11 * v11.x;
        acc.y += w00 * v00.y + w10 * v10.y + w01 * v01.y + w11 * v11.y;
    }
    out[pix * 2 + 0] = acc.x;
    out[pix * 2 + 1] = acc.y;
}

// ---------------- launch ----------------
extern "C" void kernel_launch(void* const* d_in, const int* in_sizes, int n_in,
                              void* d_out, int out_size) {
    const float* kspace_r = (const float*)d_in[0];
    const float* kspace_i = (const float*)d_in[1];
    const float* traj     = (const float*)d_in[2];
    const float* csm_r    = (const float*)d_in[3];
    const float* csm_i    = (const float*)d_in[4];
    const float* dcf      = (const float*)d_in[5];
    const float* motions  = (const float*)d_in[6];
    float* out = (float*)d_out;

    {
        size_t n4 = (size_t)NTK * 2 * G * G * 4 / 2;
        int thr = 512;
        int blk = (int)((n4 + thr - 1) / thr);
        zero_kernel<<<blk, thr>>>();
    }
    {
        dim3 grid(MK / 256, NTK);
        grid_kernel<<<grid, 256>>>(kspace_r, kspace_i, traj, dcf);
    }
    fft_rows_kernel<<<NTK * 2 * G, FT>>>();
    fft_cols_kernel<<<NTK * 2 * NXK, FT>>>();
    {
        dim3 grid((NXK * NXK + 255) / 256, NTK);
        combine_kernel<<<grid, 256>>>(csm_r, csm_i);
    }
    warp_kernel<<<(NXK * NXK + 255) / 256, 256>>>(motions, out);
}